// round 6
// baseline (speedup 1.0000x reference)
#include <cuda_runtime.h>
#include <stdint.h>

// Problem constants (from reference)
#define GX 352
#define GY 400
#define GZ 1
#define NB 4
#define NSEG (NB * GZ * GY * GX)   // 563200
#define NC 4
#define NP 2000000

// Output layout: [mean: NSEG*NC floats][counts: NSEG floats]
#define OUT_TOTAL (NSEG * (NC + 1)) // 2816000 (divisible by 4)

// ---------------------------------------------------------------------------
// Kernel 1: zero the output buffer (poisoned to 0xAA by harness)
// ---------------------------------------------------------------------------
__global__ void zero_out_kernel(float4* __restrict__ out, int n4) {
    int i = blockIdx.x * blockDim.x + threadIdx.x;
    if (i < n4) out[i] = make_float4(0.f, 0.f, 0.f, 0.f);
}

// ---------------------------------------------------------------------------
// Kernel 2: scatter-add features + counts via L2 reductions (no return value)
// One thread per point. Features go as a single red.global.add.v4.f32,
// the count as red.global.add.f32 — 2 RED ops per point total.
// ---------------------------------------------------------------------------
__global__ void scatter_add_kernel(const float4* __restrict__ features,
                                   const int4* __restrict__ coors,
                                   float* __restrict__ sums,      // NSEG*4
                                   float* __restrict__ counts) {  // NSEG
    int i = blockIdx.x * blockDim.x + threadIdx.x;
    if (i >= NP) return;

    int4 c = coors[i];                  // (b, z, y, x)
    // seg = ((b*GZ + z)*GY + y)*GX + x
    int seg = ((c.x * GZ + c.y) * GY + c.z) * GX + c.w;

    float4 f = features[i];
    float* dst = sums + (size_t)seg * NC;   // 16B aligned (seg*16 bytes)

    asm volatile("red.global.add.v4.f32 [%0], {%1, %2, %3, %4};"
                 :: "l"(dst), "f"(f.x), "f"(f.y), "f"(f.z), "f"(f.w)
                 : "memory");
    asm volatile("red.global.add.f32 [%0], %1;"
                 :: "l"(counts + seg), "f"(1.0f)
                 : "memory");
}

// ---------------------------------------------------------------------------
// Kernel 3: divide sums by max(count, 1) in place
// One thread per segment; float4 read-modify-write stays in L2.
// ---------------------------------------------------------------------------
__global__ void divide_kernel(float4* __restrict__ sums,        // NSEG float4s
                              const float* __restrict__ counts) {
    int seg = blockIdx.x * blockDim.x + threadIdx.x;
    if (seg >= NSEG) return;

    float cnt = counts[seg];
    float inv = 1.0f / fmaxf(cnt, 1.0f);
    float4 s = sums[seg];
    s.x *= inv; s.y *= inv; s.z *= inv; s.w *= inv;
    sums[seg] = s;
}

// ---------------------------------------------------------------------------
// Launcher
// ---------------------------------------------------------------------------
extern "C" void kernel_launch(void* const* d_in, const int* in_sizes, int n_in,
                              void* d_out, int out_size) {
    const float4* features = (const float4*)d_in[0];  // (NP, 4) fp32
    const int4*   coors    = (const int4*)d_in[1];    // (NP, 4) int32

    float* out    = (float*)d_out;
    float* sums   = out;                 // NSEG*4
    float* counts = out + NSEG * NC;     // NSEG

    // 1. zero the whole output region
    {
        int n4 = OUT_TOTAL / 4;          // 704000
        int threads = 256;
        int blocks = (n4 + threads - 1) / threads;
        zero_out_kernel<<<blocks, threads>>>((float4*)d_out, n4);
    }

    // 2. scatter-add points
    {
        int threads = 256;
        int blocks = (NP + threads - 1) / threads;
        scatter_add_kernel<<<blocks, threads>>>(features, coors, sums, counts);
    }

    // 3. normalize to mean
    {
        int threads = 256;
        int blocks = (NSEG + threads - 1) / threads;
        divide_kernel<<<blocks, threads>>>((float4*)sums, counts);
    }
}

// round 7
// speedup vs baseline: 1.0061x; 1.0061x over previous
#include <cuda_runtime.h>
#include <stdint.h>

// Problem constants (from reference)
#define GX 352
#define GY 400
#define GZ 1
#define NB 4
#define NSEG (NB * GZ * GY * GX)    // 563200
#define NC 4
#define NP 2000000

// Output layout: [mean: NSEG*NC floats][counts: NSEG floats]
#define OUT_TOTAL (NSEG * (NC + 1)) // 2816000 floats

// ---------------------------------------------------------------------------
// Scatter-add: 2 points per thread, loads front-batched for MLP, then REDs.
// GZ == 1, so seg = (b*GY + y)*GX + x.
// ---------------------------------------------------------------------------
__global__ void __launch_bounds__(256)
scatter_add_kernel(const float4* __restrict__ features,
                   const int4*   __restrict__ coors,
                   float*        __restrict__ sums,     // NSEG*4
                   float*        __restrict__ counts) { // NSEG
    int i = (blockIdx.x * blockDim.x + threadIdx.x) * 2;

    if (i + 1 < NP) {
        // front-batch all 4 loads (independent, coalesced 128B lines)
        int4   c0 = __ldg(coors + i);
        int4   c1 = __ldg(coors + i + 1);
        float4 f0 = __ldg(features + i);
        float4 f1 = __ldg(features + i + 1);

        int seg0 = (c0.x * GY + c0.z) * GX + c0.w;   // (b*GY + y)*GX + x
        int seg1 = (c1.x * GY + c1.z) * GX + c1.w;

        float* d0 = sums + (size_t)seg0 * NC;
        float* d1 = sums + (size_t)seg1 * NC;

        asm volatile("red.global.add.v4.f32 [%0], {%1, %2, %3, %4};"
                     :: "l"(d0), "f"(f0.x), "f"(f0.y), "f"(f0.z), "f"(f0.w)
                     : "memory");
        asm volatile("red.global.add.v4.f32 [%0], {%1, %2, %3, %4};"
                     :: "l"(d1), "f"(f1.x), "f"(f1.y), "f"(f1.z), "f"(f1.w)
                     : "memory");
        asm volatile("red.global.add.f32 [%0], %1;"
                     :: "l"(counts + seg0), "f"(1.0f) : "memory");
        asm volatile("red.global.add.f32 [%0], %1;"
                     :: "l"(counts + seg1), "f"(1.0f) : "memory");
    } else if (i < NP) {
        int4   c = __ldg(coors + i);
        float4 f = __ldg(features + i);
        int seg = (c.x * GY + c.z) * GX + c.w;
        float* d = sums + (size_t)seg * NC;
        asm volatile("red.global.add.v4.f32 [%0], {%1, %2, %3, %4};"
                     :: "l"(d), "f"(f.x), "f"(f.y), "f"(f.z), "f"(f.w)
                     : "memory");
        asm volatile("red.global.add.f32 [%0], %1;"
                     :: "l"(counts + seg), "f"(1.0f) : "memory");
    }
}

// ---------------------------------------------------------------------------
// Divide: 2 segments per thread, loads batched before use.
// ---------------------------------------------------------------------------
__global__ void __launch_bounds__(256)
divide_kernel(float4* __restrict__ sums,          // NSEG float4s
              const float* __restrict__ counts) { // NSEG
    int seg = (blockIdx.x * blockDim.x + threadIdx.x) * 2;
    if (seg + 1 < NSEG) {
        float  c0 = counts[seg];
        float  c1 = counts[seg + 1];
        float4 s0 = sums[seg];
        float4 s1 = sums[seg + 1];
        float inv0 = 1.0f / fmaxf(c0, 1.0f);
        float inv1 = 1.0f / fmaxf(c1, 1.0f);
        s0.x *= inv0; s0.y *= inv0; s0.z *= inv0; s0.w *= inv0;
        s1.x *= inv1; s1.y *= inv1; s1.z *= inv1; s1.w *= inv1;
        sums[seg]     = s0;
        sums[seg + 1] = s1;
    } else if (seg < NSEG) {
        float  c = counts[seg];
        float4 s = sums[seg];
        float inv = 1.0f / fmaxf(c, 1.0f);
        s.x *= inv; s.y *= inv; s.z *= inv; s.w *= inv;
        sums[seg] = s;
    }
}

// ---------------------------------------------------------------------------
// Launcher
// ---------------------------------------------------------------------------
extern "C" void kernel_launch(void* const* d_in, const int* in_sizes, int n_in,
                              void* d_out, int out_size) {
    const float4* features = (const float4*)d_in[0];  // (NP, 4) fp32
    const int4*   coors    = (const int4*)d_in[1];    // (NP, 4) int32

    float* out    = (float*)d_out;
    float* sums   = out;                 // NSEG*4
    float* counts = out + NSEG * NC;     // NSEG

    // 1. zero the whole output region (graph-capturable memset node)
    cudaMemsetAsync(d_out, 0, (size_t)OUT_TOTAL * sizeof(float));

    // 2. scatter-add points (2 points per thread)
    {
        int threads = 256;
        int work = (NP + 1) / 2;
        int blocks = (work + threads - 1) / threads;
        scatter_add_kernel<<<blocks, threads>>>(features, coors, sums, counts);
    }

    // 3. normalize to mean (2 segments per thread)
    {
        int threads = 256;
        int work = (NSEG + 1) / 2;
        int blocks = (work + threads - 1) / threads;
        divide_kernel<<<blocks, threads>>>((float4*)sums, counts);
    }
}